// round 3
// baseline (speedup 1.0000x reference)
#include <cuda_runtime.h>
#include <stdint.h>

#define NN 100000
#define NE 3200000
#define NG 1000

// ---------------- scratch (module-load device globals, allowed) ----------------
__device__ float g_deg[NN];
__device__ float g_dinv[NN];
__device__ int   g_cnt[NN];
__device__ int   g_cur[NN];         // exclusive offsets; == segment end after scatter
__device__ int2  g_csr[NE];         // {src_node, norm as float bits}, grouped by dst
__device__ float g_a1[NN * 16];     // relu(layer1 out) = layer2 input features
__device__ float g_pool[NG * 16];
__device__ int   g_is64;            // 1 if integer inputs are int64, 0 if int32

// Uniform-branch index load (dtype decided at runtime by probe kernel).
__device__ __forceinline__ int idx_at(const void* p, long long i, int is64) {
    if (is64) return (int)((const long long*)p)[i];
    return ((const int*)p)[i];
}

// ---------------- kernels ----------------

__global__ void __launch_bounds__(256) k_init() {
    int i = blockIdx.x * blockDim.x + threadIdx.x;
    if (i == 0) g_is64 = 1;
    if (i < NN) { g_deg[i] = 1.0f; g_cnt[i] = 0; }   // deg starts at 1.0 (self-loop weight)
    if (i < NG * 16) g_pool[i] = 0.0f;
}

// Probe: int64 data (values in [0,1e5)) has all-zero high words at odd int32
// positions; int32 data has random node ids there -> any nonzero clears flag.
__global__ void __launch_bounds__(256) k_detect(const int* __restrict__ ei32) {
    int t = blockIdx.x * blockDim.x + threadIdx.x;
    if (t < 4096 && ei32[2 * t + 1] != 0) g_is64 = 0;
}

__global__ void __launch_bounds__(256) k_deg_hist(const void* __restrict__ ei,
                                                  const float* __restrict__ ew) {
    int is64 = g_is64;
    int e = blockIdx.x * blockDim.x + threadIdx.x;
    if (e >= NE) return;
    int c = idx_at(ei, (long long)NE + e, is64);
    atomicAdd(&g_deg[c], ew[e]);
    atomicAdd(&g_cnt[c], 1);
}

// single-block exclusive scan of g_cnt -> g_cur (100k elements)
__global__ void __launch_bounds__(1024, 1) k_scan() {
    __shared__ int sh[1024];
    const int CH = (NN + 1023) / 1024;   // 98 per thread
    int t = threadIdx.x;
    int base = t * CH;
    int s = 0;
    for (int j = 0; j < CH; j++) { int idx = base + j; if (idx < NN) s += g_cnt[idx]; }
    sh[t] = s;
    __syncthreads();
    for (int off = 1; off < 1024; off <<= 1) {
        int v = (t >= off) ? sh[t - off] : 0;
        __syncthreads();
        sh[t] += v;
        __syncthreads();
    }
    int run = (t == 0) ? 0 : sh[t - 1];
    for (int j = 0; j < CH; j++) {
        int idx = base + j;
        if (idx < NN) { g_cur[idx] = run; run += g_cnt[idx]; }
    }
}

__global__ void __launch_bounds__(256) k_dinv() {
    int i = blockIdx.x * blockDim.x + threadIdx.x;
    if (i < NN) g_dinv[i] = rsqrtf(g_deg[i]);   // deg >= 1 always (self-loop)
}

__global__ void __launch_bounds__(256) k_scatter(const void* __restrict__ ei,
                                                 const float* __restrict__ ew) {
    int is64 = g_is64;
    int e = blockIdx.x * blockDim.x + threadIdx.x;
    if (e >= NE) return;
    int r = idx_at(ei, e, is64);
    int c = idx_at(ei, (long long)NE + e, is64);
    float nrm = g_dinv[r] * ew[e] * g_dinv[c];
    int pos = atomicAdd(&g_cur[c], 1);
    g_csr[pos] = make_int2(r, __float_as_int(nrm));
}

// Layer 1: aggregate 3-dim raw features per dst node (warp/node), then @W1, relu.
// Uses linearity: sum(norm * (x[r]@W1)) = (sum(norm * x[r])) @ W1.
__global__ void __launch_bounds__(256) k_layer1(const float* __restrict__ x,
                                                const float* __restrict__ W1,
                                                const float* __restrict__ b1) {
    int wid = (blockIdx.x * blockDim.x + threadIdx.x) >> 5;
    int lane = threadIdx.x & 31;
    if (wid >= NN) return;
    int end = g_cur[wid];
    int n = g_cnt[wid];
    float s0 = 0.f, s1 = 0.f, s2 = 0.f;
    for (int e = end - n + lane; e < end; e += 32) {
        int2 p = g_csr[e];
        float nrm = __int_as_float(p.y);
        const float* xr = x + 3 * p.x;
        s0 += nrm * xr[0];
        s1 += nrm * xr[1];
        s2 += nrm * xr[2];
    }
#pragma unroll
    for (int off = 16; off; off >>= 1) {
        s0 += __shfl_xor_sync(0xffffffffu, s0, off);
        s1 += __shfl_xor_sync(0xffffffffu, s1, off);
        s2 += __shfl_xor_sync(0xffffffffu, s2, off);
    }
    float di = g_dinv[wid];
    float d2 = di * di;                     // self-loop norm = dinv^2 (w=1)
    s0 += d2 * x[3 * wid];
    s1 += d2 * x[3 * wid + 1];
    s2 += d2 * x[3 * wid + 2];
    if (lane < 16) {
        float o = b1[lane] + s0 * W1[lane] + s1 * W1[16 + lane] + s2 * W1[32 + lane];
        g_a1[wid * 16 + lane] = fmaxf(o, 0.0f);
    }
}

// Layer 2: warp/node; two half-warps stream edges, 16 lanes = 16 features
// (coalesced 64B gathers of a1 rows). Then 16x16 matmul via shuffles,
// relu, atomic pool into per-graph accumulator.
__global__ void __launch_bounds__(256) k_layer2(const float* __restrict__ W2,
                                                const float* __restrict__ b2,
                                                const void* __restrict__ batch) {
    int is64 = g_is64;
    int wid = (blockIdx.x * blockDim.x + threadIdx.x) >> 5;
    int lane = threadIdx.x & 31;
    if (wid >= NN) return;
    int f = lane & 15;
    int half = lane >> 4;
    int end = g_cur[wid];
    int n = g_cnt[wid];
    float acc = 0.0f;
    for (int e = end - n + half; e < end; e += 2) {
        int2 p = g_csr[e];
        acc += __int_as_float(p.y) * g_a1[p.x * 16 + f];
    }
    acc += __shfl_xor_sync(0xffffffffu, acc, 16);
    float di = g_dinv[wid];
    acc += di * di * g_a1[wid * 16 + f];    // self-loop term
    float o = b2[f];
#pragma unroll
    for (int k = 0; k < 16; k++) {
        float v = __shfl_sync(0xffffffffu, acc, k);
        o += v * W2[k * 16 + f];
    }
    o = fmaxf(o, 0.0f);
    if (half == 0) {
        int g = idx_at(batch, wid, is64);
        atomicAdd(&g_pool[g * 16 + f], o);
    }
}

__global__ void __launch_bounds__(256) k_final(const float* __restrict__ Wlin,
                                               const float* __restrict__ blin,
                                               float* __restrict__ out) {
    int t = blockIdx.x * blockDim.x + threadIdx.x;
    if (t >= NG * 7) return;
    int g = t / 7, j = t % 7;
    float o = blin[j];
#pragma unroll
    for (int k = 0; k < 16; k++) o += g_pool[g * 16 + k] * Wlin[k * 7 + j];
    out[t] = o;
}

// ---------------- launch ----------------

extern "C" void kernel_launch(void* const* d_in, const int* in_sizes, int n_in,
                              void* d_out, int out_size) {
    const float* x     = (const float*)d_in[0];
    const void*  ei    = d_in[1];
    const float* ew    = (const float*)d_in[2];
    const void*  batch = d_in[3];
    const float* W1    = (const float*)d_in[4];
    const float* b1    = (const float*)d_in[5];
    const float* W2    = (const float*)d_in[6];
    const float* b2    = (const float*)d_in[7];
    const float* Wlin  = (const float*)d_in[8];
    const float* blin  = (const float*)d_in[9];
    float* out = (float*)d_out;

    k_init    <<<(NN + 255) / 256, 256>>>();
    k_detect  <<<16, 256>>>((const int*)ei);
    k_deg_hist<<<(NE + 255) / 256, 256>>>(ei, ew);
    k_scan    <<<1, 1024>>>();
    k_dinv    <<<(NN + 255) / 256, 256>>>();
    k_scatter <<<(NE + 255) / 256, 256>>>(ei, ew);
    k_layer1  <<<(NN * 32 + 255) / 256, 256>>>(x, W1, b1);
    k_layer2  <<<(NN * 32 + 255) / 256, 256>>>(W2, b2, batch);
    k_final   <<<(NG * 7 + 255) / 256, 256>>>(Wlin, blin, out);
}

// round 4
// speedup vs baseline: 1.5469x; 1.5469x over previous
#include <cuda_runtime.h>
#include <stdint.h>

#define NN 100000
#define NE 3200000
#define NG 1000

#define SCAN_CHUNK 1024
#define NSB ((NN + SCAN_CHUNK - 1) / SCAN_CHUNK)   // 98 blocks

// ---------------- scratch (module-load device globals, allowed) ----------------
__device__ float g_deg[NN];
__device__ float g_dinv[NN];
__device__ int   g_cnt[NN];
__device__ int   g_cur[NN];         // exclusive offsets; == segment end after scatter
__device__ int   g_bsum[NSB];       // per-block sums for decoupled scan
__device__ int2  g_csr[NE];         // {src_node, norm as float bits}, grouped by dst
__device__ float g_a1[NN * 16];     // relu(layer1 out) = layer2 input features
__device__ float g_pool[NG * 16];
__device__ int   g_is64;            // 1 if integer inputs are int64, 0 if int32

// Uniform-branch index load (dtype decided at runtime by probe kernel).
__device__ __forceinline__ int idx_at(const void* p, long long i, int is64) {
    if (is64) return (int)((const long long*)p)[i];
    return ((const int*)p)[i];
}

// ---------------- kernels ----------------

__global__ void __launch_bounds__(256) k_init() {
    int i = blockIdx.x * blockDim.x + threadIdx.x;
    if (i == 0) g_is64 = 1;
    if (i < NN) { g_deg[i] = 1.0f; g_cnt[i] = 0; }   // deg starts at 1.0 (self-loop weight)
    if (i < NG * 16) g_pool[i] = 0.0f;
}

// Probe: int64 data (values in [0,1e5)) has all-zero high words at odd int32
// positions; int32 data has random node ids there -> any nonzero clears flag.
__global__ void __launch_bounds__(256) k_detect(const int* __restrict__ ei32) {
    int t = blockIdx.x * blockDim.x + threadIdx.x;
    if (t < 4096 && ei32[2 * t + 1] != 0) g_is64 = 0;
}

__global__ void __launch_bounds__(256) k_deg_hist(const void* __restrict__ ei,
                                                  const float* __restrict__ ew) {
    int is64 = g_is64;
    int e = blockIdx.x * blockDim.x + threadIdx.x;
    if (e >= NE) return;
    int c = idx_at(ei, (long long)NE + e, is64);
    atomicAdd(&g_deg[c], ew[e]);
    atomicAdd(&g_cnt[c], 1);
}

// ---- decoupled 3-phase exclusive scan of g_cnt -> g_cur ----

// Phase 1: per-block reduce (each block owns 1024 counts, 4 per thread).
__global__ void __launch_bounds__(256) k_scan1() {
    int b = blockIdx.x, t = threadIdx.x;
    int base = b * SCAN_CHUNK + t * 4;
    int s = 0;
#pragma unroll
    for (int j = 0; j < 4; j++) { int i = base + j; if (i < NN) s += g_cnt[i]; }
#pragma unroll
    for (int off = 16; off; off >>= 1) s += __shfl_xor_sync(0xffffffffu, s, off);
    __shared__ int wsum[8];
    if ((t & 31) == 0) wsum[t >> 5] = s;
    __syncthreads();
    if (t == 0) {
        int tot = 0;
#pragma unroll
        for (int w = 0; w < 8; w++) tot += wsum[w];
        g_bsum[b] = tot;
    }
}

// Phase 2: one small block scans the 98 block sums (exclusive).
__global__ void __launch_bounds__(128) k_scan2() {
    __shared__ int sh[128];
    int t = threadIdx.x;
    int v = (t < NSB) ? g_bsum[t] : 0;
    sh[t] = v;
    __syncthreads();
    for (int off = 1; off < 128; off <<= 1) {
        int u = (t >= off) ? sh[t - off] : 0;
        __syncthreads();
        sh[t] += u;
        __syncthreads();
    }
    if (t < NSB) g_bsum[t] = sh[t] - v;   // exclusive
}

// Phase 3: in-block exclusive scan + block offset -> g_cur.
__global__ void __launch_bounds__(256) k_scan3() {
    __shared__ int woff[8];
    int b = blockIdx.x, t = threadIdx.x;
    int lane = t & 31, w = t >> 5;
    int base = b * SCAN_CHUNK + t * 4;
    int v[4];
    int ts = 0;
#pragma unroll
    for (int j = 0; j < 4; j++) {
        int i = base + j;
        v[j] = (i < NN) ? g_cnt[i] : 0;
        ts += v[j];
    }
    // inclusive warp scan of thread sums
    int inc = ts;
#pragma unroll
    for (int off = 1; off < 32; off <<= 1) {
        int u = __shfl_up_sync(0xffffffffu, inc, off);
        if (lane >= off) inc += u;
    }
    if (lane == 31) woff[w] = inc;
    __syncthreads();
    if (t == 0) {
        int run = 0;
#pragma unroll
        for (int i = 0; i < 8; i++) { int u = woff[i]; woff[i] = run; run += u; }
    }
    __syncthreads();
    int run = g_bsum[b] + woff[w] + (inc - ts);   // exclusive prefix for this thread
#pragma unroll
    for (int j = 0; j < 4; j++) {
        int i = base + j;
        if (i < NN) g_cur[i] = run;
        run += v[j];
    }
}

__global__ void __launch_bounds__(256) k_dinv() {
    int i = blockIdx.x * blockDim.x + threadIdx.x;
    if (i < NN) g_dinv[i] = rsqrtf(g_deg[i]);   // deg >= 1 always (self-loop)
}

__global__ void __launch_bounds__(256) k_scatter(const void* __restrict__ ei,
                                                 const float* __restrict__ ew) {
    int is64 = g_is64;
    int e = blockIdx.x * blockDim.x + threadIdx.x;
    if (e >= NE) return;
    int r = idx_at(ei, e, is64);
    int c = idx_at(ei, (long long)NE + e, is64);
    float nrm = g_dinv[r] * ew[e] * g_dinv[c];
    int pos = atomicAdd(&g_cur[c], 1);
    g_csr[pos] = make_int2(r, __float_as_int(nrm));
}

// Layer 1: aggregate 3-dim raw features per dst node (warp/node), then @W1, relu.
// Uses linearity: sum(norm * (x[r]@W1)) = (sum(norm * x[r])) @ W1.
__global__ void __launch_bounds__(256) k_layer1(const float* __restrict__ x,
                                                const float* __restrict__ W1,
                                                const float* __restrict__ b1) {
    int wid = (blockIdx.x * blockDim.x + threadIdx.x) >> 5;
    int lane = threadIdx.x & 31;
    if (wid >= NN) return;
    int end = g_cur[wid];
    int n = g_cnt[wid];
    float s0 = 0.f, s1 = 0.f, s2 = 0.f;
    for (int e = end - n + lane; e < end; e += 32) {
        int2 p = g_csr[e];
        float nrm = __int_as_float(p.y);
        const float* xr = x + 3 * p.x;
        s0 += nrm * xr[0];
        s1 += nrm * xr[1];
        s2 += nrm * xr[2];
    }
#pragma unroll
    for (int off = 16; off; off >>= 1) {
        s0 += __shfl_xor_sync(0xffffffffu, s0, off);
        s1 += __shfl_xor_sync(0xffffffffu, s1, off);
        s2 += __shfl_xor_sync(0xffffffffu, s2, off);
    }
    float di = g_dinv[wid];
    float d2 = di * di;                     // self-loop norm = dinv^2 (w=1)
    s0 += d2 * x[3 * wid];
    s1 += d2 * x[3 * wid + 1];
    s2 += d2 * x[3 * wid + 2];
    if (lane < 16) {
        float o = b1[lane] + s0 * W1[lane] + s1 * W1[16 + lane] + s2 * W1[32 + lane];
        g_a1[wid * 16 + lane] = fmaxf(o, 0.0f);
    }
}

// Layer 2: warp/node; two half-warps stream edges, 16 lanes = 16 features
// (coalesced 64B gathers of a1 rows). Then 16x16 matmul via shuffles,
// relu, atomic pool into per-graph accumulator.
__global__ void __launch_bounds__(256) k_layer2(const float* __restrict__ W2,
                                                const float* __restrict__ b2,
                                                const void* __restrict__ batch) {
    int is64 = g_is64;
    int wid = (blockIdx.x * blockDim.x + threadIdx.x) >> 5;
    int lane = threadIdx.x & 31;
    if (wid >= NN) return;
    int f = lane & 15;
    int half = lane >> 4;
    int end = g_cur[wid];
    int n = g_cnt[wid];
    float acc = 0.0f;
    for (int e = end - n + half; e < end; e += 2) {
        int2 p = g_csr[e];
        acc += __int_as_float(p.y) * g_a1[p.x * 16 + f];
    }
    acc += __shfl_xor_sync(0xffffffffu, acc, 16);
    float di = g_dinv[wid];
    acc += di * di * g_a1[wid * 16 + f];    // self-loop term
    float o = b2[f];
#pragma unroll
    for (int k = 0; k < 16; k++) {
        float v = __shfl_sync(0xffffffffu, acc, k);
        o += v * W2[k * 16 + f];
    }
    o = fmaxf(o, 0.0f);
    if (half == 0) {
        int g = idx_at(batch, wid, is64);
        atomicAdd(&g_pool[g * 16 + f], o);
    }
}

__global__ void __launch_bounds__(256) k_final(const float* __restrict__ Wlin,
                                               const float* __restrict__ blin,
                                               float* __restrict__ out) {
    int t = blockIdx.x * blockDim.x + threadIdx.x;
    if (t >= NG * 7) return;
    int g = t / 7, j = t % 7;
    float o = blin[j];
#pragma unroll
    for (int k = 0; k < 16; k++) o += g_pool[g * 16 + k] * Wlin[k * 7 + j];
    out[t] = o;
}

// ---------------- launch ----------------

extern "C" void kernel_launch(void* const* d_in, const int* in_sizes, int n_in,
                              void* d_out, int out_size) {
    const float* x     = (const float*)d_in[0];
    const void*  ei    = d_in[1];
    const float* ew    = (const float*)d_in[2];
    const void*  batch = d_in[3];
    const float* W1    = (const float*)d_in[4];
    const float* b1    = (const float*)d_in[5];
    const float* W2    = (const float*)d_in[6];
    const float* b2    = (const float*)d_in[7];
    const float* Wlin  = (const float*)d_in[8];
    const float* blin  = (const float*)d_in[9];
    float* out = (float*)d_out;

    k_init    <<<(NN + 255) / 256, 256>>>();
    k_detect  <<<16, 256>>>((const int*)ei);
    k_deg_hist<<<(NE + 255) / 256, 256>>>(ei, ew);
    k_scan1   <<<NSB, 256>>>();
    k_scan2   <<<1, 128>>>();
    k_scan3   <<<NSB, 256>>>();
    k_dinv    <<<(NN + 255) / 256, 256>>>();
    k_scatter <<<(NE + 255) / 256, 256>>>(ei, ew);
    k_layer1  <<<(NN * 32 + 255) / 256, 256>>>(x, W1, b1);
    k_layer2  <<<(NN * 32 + 255) / 256, 256>>>(W2, b2, batch);
    k_final   <<<(NG * 7 + 255) / 256, 256>>>(Wlin, blin, out);
}

// round 5
// speedup vs baseline: 1.6217x; 1.0484x over previous
#include <cuda_runtime.h>
#include <cuda_fp16.h>
#include <stdint.h>

#define NN 100000
#define NE 3200000
#define NG 1000

#define SCAN_CHUNK 1024
#define NSB ((NN + SCAN_CHUNK - 1) / SCAN_CHUNK)   // 98 blocks

// ---------------- scratch (module-load device globals, allowed) ----------------
__device__ float  g_deg[NN];
__device__ float  g_dinv[NN];
__device__ int    g_cnt[NN];
__device__ int    g_cur[NN];        // exclusive offsets; == segment end after scatter
__device__ int    g_bsum[NSB];      // per-block sums for decoupled scan
__device__ int2   g_csr[NE];        // {src_node, norm as float bits}, grouped by dst
__device__ float4 g_x4[NN];         // x padded to 16B rows (1 sector per gather)
__device__ __half g_a1h[NN * 16];   // relu(layer1 out), fp16 (32B rows = 1 sector)
__device__ float  g_pool[NG * 16];
__device__ int    g_is64;           // 1 if integer inputs are int64, 0 if int32

// Uniform-branch index load (dtype decided at runtime by probe kernel).
__device__ __forceinline__ int idx_at(const void* p, long long i, int is64) {
    if (is64) return (int)((const long long*)p)[i];
    return ((const int*)p)[i];
}

// ---------------- kernels ----------------

__global__ void __launch_bounds__(256) k_init(const float* __restrict__ x) {
    int i = blockIdx.x * blockDim.x + threadIdx.x;
    if (i == 0) g_is64 = 1;
    if (i < NN) {
        g_deg[i] = 1.0f;                 // self-loop weight
        g_cnt[i] = 0;
        g_x4[i] = make_float4(x[3 * i], x[3 * i + 1], x[3 * i + 2], 0.0f);
    }
    if (i < NG * 16) g_pool[i] = 0.0f;
}

// Probe: int64 data (values in [0,1e5)) has all-zero high words at odd int32
// positions; int32 data has random node ids there -> any nonzero clears flag.
__global__ void __launch_bounds__(256) k_detect(const int* __restrict__ ei32) {
    int t = blockIdx.x * blockDim.x + threadIdx.x;
    if (t < 4096 && ei32[2 * t + 1] != 0) g_is64 = 0;
}

__global__ void __launch_bounds__(256) k_deg_hist(const void* __restrict__ ei,
                                                  const float* __restrict__ ew) {
    int is64 = g_is64;
    int e = blockIdx.x * blockDim.x + threadIdx.x;
    if (e >= NE) return;
    int c = idx_at(ei, (long long)NE + e, is64);
    atomicAdd(&g_deg[c], ew[e]);
    atomicAdd(&g_cnt[c], 1);
}

// ---- decoupled 3-phase exclusive scan of g_cnt -> g_cur (+ fused dinv) ----

// Phase 1: per-block reduce (each block owns 1024 counts, 4 per thread).
// Also computes g_dinv for the same 4 nodes (deg is final here).
__global__ void __launch_bounds__(256) k_scan1() {
    int b = blockIdx.x, t = threadIdx.x;
    int base = b * SCAN_CHUNK + t * 4;
    int s = 0;
#pragma unroll
    for (int j = 0; j < 4; j++) {
        int i = base + j;
        if (i < NN) {
            s += g_cnt[i];
            g_dinv[i] = rsqrtf(g_deg[i]);   // deg >= 1 always (self-loop)
        }
    }
#pragma unroll
    for (int off = 16; off; off >>= 1) s += __shfl_xor_sync(0xffffffffu, s, off);
    __shared__ int wsum[8];
    if ((t & 31) == 0) wsum[t >> 5] = s;
    __syncthreads();
    if (t == 0) {
        int tot = 0;
#pragma unroll
        for (int w = 0; w < 8; w++) tot += wsum[w];
        g_bsum[b] = tot;
    }
}

// Phase 2: one small block scans the 98 block sums (exclusive).
__global__ void __launch_bounds__(128) k_scan2() {
    __shared__ int sh[128];
    int t = threadIdx.x;
    int v = (t < NSB) ? g_bsum[t] : 0;
    sh[t] = v;
    __syncthreads();
    for (int off = 1; off < 128; off <<= 1) {
        int u = (t >= off) ? sh[t - off] : 0;
        __syncthreads();
        sh[t] += u;
        __syncthreads();
    }
    if (t < NSB) g_bsum[t] = sh[t] - v;   // exclusive
}

// Phase 3: in-block exclusive scan + block offset -> g_cur.
__global__ void __launch_bounds__(256) k_scan3() {
    __shared__ int woff[8];
    int b = blockIdx.x, t = threadIdx.x;
    int lane = t & 31, w = t >> 5;
    int base = b * SCAN_CHUNK + t * 4;
    int v[4];
    int ts = 0;
#pragma unroll
    for (int j = 0; j < 4; j++) {
        int i = base + j;
        v[j] = (i < NN) ? g_cnt[i] : 0;
        ts += v[j];
    }
    int inc = ts;
#pragma unroll
    for (int off = 1; off < 32; off <<= 1) {
        int u = __shfl_up_sync(0xffffffffu, inc, off);
        if (lane >= off) inc += u;
    }
    if (lane == 31) woff[w] = inc;
    __syncthreads();
    if (t == 0) {
        int run = 0;
#pragma unroll
        for (int i = 0; i < 8; i++) { int u = woff[i]; woff[i] = run; run += u; }
    }
    __syncthreads();
    int run = g_bsum[b] + woff[w] + (inc - ts);
#pragma unroll
    for (int j = 0; j < 4; j++) {
        int i = base + j;
        if (i < NN) g_cur[i] = run;
        run += v[j];
    }
}

__global__ void __launch_bounds__(256) k_scatter(const void* __restrict__ ei,
                                                 const float* __restrict__ ew) {
    int is64 = g_is64;
    int e = blockIdx.x * blockDim.x + threadIdx.x;
    if (e >= NE) return;
    int r = idx_at(ei, e, is64);
    int c = idx_at(ei, (long long)NE + e, is64);
    float nrm = g_dinv[r] * ew[e] * g_dinv[c];
    int pos = atomicAdd(&g_cur[c], 1);
    g_csr[pos] = make_int2(r, __float_as_int(nrm));
}

// Layer 1: aggregate padded-float4 features per dst node (warp/node, 1 edge/lane),
// then @W1, relu, store fp16. Uses GCN linearity: sum(norm*x[r]) @ W1.
__global__ void __launch_bounds__(256) k_layer1(const float* __restrict__ W1,
                                                const float* __restrict__ b1) {
    int wid = (blockIdx.x * blockDim.x + threadIdx.x) >> 5;
    int lane = threadIdx.x & 31;
    if (wid >= NN) return;
    int end = g_cur[wid];
    int n = g_cnt[wid];
    float s0 = 0.f, s1 = 0.f, s2 = 0.f;
    for (int e = end - n + lane; e < end; e += 32) {
        int2 p = g_csr[e];
        float nrm = __int_as_float(p.y);
        float4 xr = g_x4[p.x];               // one LDG.128, one sector
        s0 += nrm * xr.x;
        s1 += nrm * xr.y;
        s2 += nrm * xr.z;
    }
#pragma unroll
    for (int off = 16; off; off >>= 1) {
        s0 += __shfl_xor_sync(0xffffffffu, s0, off);
        s1 += __shfl_xor_sync(0xffffffffu, s1, off);
        s2 += __shfl_xor_sync(0xffffffffu, s2, off);
    }
    float di = g_dinv[wid];
    float d2 = di * di;                      // self-loop norm = dinv^2 (w=1)
    float4 xs = g_x4[wid];
    s0 += d2 * xs.x;
    s1 += d2 * xs.y;
    s2 += d2 * xs.z;
    if (lane < 16) {
        float o = b1[lane] + s0 * W1[lane] + s1 * W1[16 + lane] + s2 * W1[32 + lane];
        g_a1h[wid * 16 + lane] = __float2half(fmaxf(o, 0.0f));
    }
}

// Layer 2: warp/node; 4 groups of 8 lanes, each group streams one edge
// (half2 per lane = 2 features, 32B coalesced gather = 1 sector). Then
// 16x16 matmul via shuffles, relu, atomic pool.
__global__ void __launch_bounds__(256) k_layer2(const float* __restrict__ W2,
                                                const float* __restrict__ b2,
                                                const void* __restrict__ batch) {
    int is64 = g_is64;
    int wid = (blockIdx.x * blockDim.x + threadIdx.x) >> 5;
    int lane = threadIdx.x & 31;
    if (wid >= NN) return;
    const __half2* a1h2 = (const __half2*)g_a1h;
    int grp = lane >> 3;                     // 0..3
    int ff  = lane & 7;                      // feature pair index
    int end = g_cur[wid];
    int n = g_cnt[wid];
    float ax = 0.0f, ay = 0.0f;
    for (int e = end - n + grp; e < end; e += 4) {
        int2 p = g_csr[e];                   // broadcast within group
        float nrm = __int_as_float(p.y);
        float2 v = __half22float2(a1h2[p.x * 8 + ff]);
        ax += nrm * v.x;
        ay += nrm * v.y;
    }
#pragma unroll
    for (int off = 8; off <= 16; off <<= 1) {
        ax += __shfl_xor_sync(0xffffffffu, ax, off);
        ay += __shfl_xor_sync(0xffffffffu, ay, off);
    }
    float di = g_dinv[wid];
    float d2 = di * di;
    float2 vs = __half22float2(a1h2[wid * 8 + ff]);
    ax += d2 * vs.x;
    ay += d2 * vs.y;                         // all lanes now hold sums for pair ff
    int f = lane & 15;
    float o = b2[f];
#pragma unroll
    for (int k = 0; k < 16; k++) {
        float vk = __shfl_sync(0xffffffffu, (k & 1) ? ay : ax, k >> 1);
        o += vk * W2[k * 16 + f];
    }
    o = fmaxf(o, 0.0f);
    if (lane < 16) {
        int g = idx_at(batch, wid, is64);
        atomicAdd(&g_pool[g * 16 + f], o);
    }
}

__global__ void __launch_bounds__(256) k_final(const float* __restrict__ Wlin,
                                               const float* __restrict__ blin,
                                               float* __restrict__ out) {
    int t = blockIdx.x * blockDim.x + threadIdx.x;
    if (t >= NG * 7) return;
    int g = t / 7, j = t % 7;
    float o = blin[j];
#pragma unroll
    for (int k = 0; k < 16; k++) o += g_pool[g * 16 + k] * Wlin[k * 7 + j];
    out[t] = o;
}

// ---------------- launch ----------------

extern "C" void kernel_launch(void* const* d_in, const int* in_sizes, int n_in,
                              void* d_out, int out_size) {
    const float* x     = (const float*)d_in[0];
    const void*  ei    = d_in[1];
    const float* ew    = (const float*)d_in[2];
    const void*  batch = d_in[3];
    const float* W1    = (const float*)d_in[4];
    const float* b1    = (const float*)d_in[5];
    const float* W2    = (const float*)d_in[6];
    const float* b2    = (const float*)d_in[7];
    const float* Wlin  = (const float*)d_in[8];
    const float* blin  = (const float*)d_in[9];
    float* out = (float*)d_out;

    k_init    <<<(NN + 255) / 256, 256>>>(x);
    k_detect  <<<16, 256>>>((const int*)ei);
    k_deg_hist<<<(NE + 255) / 256, 256>>>(ei, ew);
    k_scan1   <<<NSB, 256>>>();
    k_scan2   <<<1, 128>>>();
    k_scan3   <<<NSB, 256>>>();
    k_scatter <<<(NE + 255) / 256, 256>>>(ei, ew);
    k_layer1  <<<(NN * 32 + 255) / 256, 256>>>(W1, b1);
    k_layer2  <<<(NN * 32 + 255) / 256, 256>>>(W2, b2, batch);
    k_final   <<<(NG * 7 + 255) / 256, 256>>>(Wlin, blin, out);
}

// round 6
// speedup vs baseline: 1.6874x; 1.0405x over previous
#include <cuda_runtime.h>
#include <cuda_fp16.h>
#include <stdint.h>

#define NN 100000
#define NE 3200000
#define NG 1000

#define SCAN_CHUNK 1024
#define NSB ((NN + SCAN_CHUNK - 1) / SCAN_CHUNK)   // 98 blocks

// ---------------- scratch (module-load device globals, allowed) ----------------
__device__ float  g_dinv[NN];
__device__ int    g_cnt[NN];
__device__ int    g_cur[NN];        // exclusive offsets; == segment end after scatter
__device__ int    g_bsum[NSB];      // per-block sums for decoupled scan
__device__ int2   g_csr[NE];        // {src_node, edge_weight bits}, grouped by dst
__device__ float4 g_x4[NN];         // x padded; after k_deg: premultiplied by dinv
__device__ __half g_a1h[NN * 16];   // dinv * relu(layer1 out), fp16 (32B rows)
__device__ float  g_pool[NG * 16];
__device__ int    g_is64;           // 1 if integer inputs are int64, 0 if int32

// Uniform-branch index load (dtype decided at runtime by probe kernel).
__device__ __forceinline__ int idx_at(const void* p, long long i, int is64) {
    if (is64) return (int)((const long long*)p)[i];
    return ((const int*)p)[i];
}

// ---------------- kernels ----------------

__global__ void __launch_bounds__(256) k_init(const float* __restrict__ x) {
    int i = blockIdx.x * blockDim.x + threadIdx.x;
    if (i == 0) g_is64 = 1;
    if (i < NN) {
        g_cnt[i] = 0;
        g_x4[i] = make_float4(x[3 * i], x[3 * i + 1], x[3 * i + 2], 0.0f);
    }
    if (i < NG * 16) g_pool[i] = 0.0f;
}

// Probe: int64 data (values in [0,1e5)) has all-zero high words at odd int32
// positions; int32 data has random node ids there -> any nonzero clears flag.
__global__ void __launch_bounds__(256) k_detect(const int* __restrict__ ei32) {
    int t = blockIdx.x * blockDim.x + threadIdx.x;
    if (t < 4096 && ei32[2 * t + 1] != 0) g_is64 = 0;
}

// Pad launch: positions k_hist at launch index 3 (the index ncu profiles).
__global__ void k_pad() {}

// Count-only histogram over destination nodes (no float atomics anymore).
__global__ void __launch_bounds__(256) k_hist(const void* __restrict__ ei) {
    int is64 = g_is64;
    int e = blockIdx.x * blockDim.x + threadIdx.x;
    if (e >= NE) return;
    int c = idx_at(ei, (long long)NE + e, is64);
    atomicAdd(&g_cnt[c], 1);
}

// ---- decoupled 3-phase exclusive scan of g_cnt -> g_cur ----

__global__ void __launch_bounds__(256) k_scan1() {
    int b = blockIdx.x, t = threadIdx.x;
    int base = b * SCAN_CHUNK + t * 4;
    int s = 0;
#pragma unroll
    for (int j = 0; j < 4; j++) { int i = base + j; if (i < NN) s += g_cnt[i]; }
#pragma unroll
    for (int off = 16; off; off >>= 1) s += __shfl_xor_sync(0xffffffffu, s, off);
    __shared__ int wsum[8];
    if ((t & 31) == 0) wsum[t >> 5] = s;
    __syncthreads();
    if (t == 0) {
        int tot = 0;
#pragma unroll
        for (int w = 0; w < 8; w++) tot += wsum[w];
        g_bsum[b] = tot;
    }
}

__global__ void __launch_bounds__(128) k_scan2() {
    __shared__ int sh[128];
    int t = threadIdx.x;
    int v = (t < NSB) ? g_bsum[t] : 0;
    sh[t] = v;
    __syncthreads();
    for (int off = 1; off < 128; off <<= 1) {
        int u = (t >= off) ? sh[t - off] : 0;
        __syncthreads();
        sh[t] += u;
        __syncthreads();
    }
    if (t < NSB) g_bsum[t] = sh[t] - v;   // exclusive
}

__global__ void __launch_bounds__(256) k_scan3() {
    __shared__ int woff[8];
    int b = blockIdx.x, t = threadIdx.x;
    int lane = t & 31, w = t >> 5;
    int base = b * SCAN_CHUNK + t * 4;
    int v[4];
    int ts = 0;
#pragma unroll
    for (int j = 0; j < 4; j++) {
        int i = base + j;
        v[j] = (i < NN) ? g_cnt[i] : 0;
        ts += v[j];
    }
    int inc = ts;
#pragma unroll
    for (int off = 1; off < 32; off <<= 1) {
        int u = __shfl_up_sync(0xffffffffu, inc, off);
        if (lane >= off) inc += u;
    }
    if (lane == 31) woff[w] = inc;
    __syncthreads();
    if (t == 0) {
        int run = 0;
#pragma unroll
        for (int i = 0; i < 8; i++) { int u = woff[i]; woff[i] = run; run += u; }
    }
    __syncthreads();
    int run = g_bsum[b] + woff[w] + (inc - ts);
#pragma unroll
    for (int j = 0; j < 4; j++) {
        int i = base + j;
        if (i < NN) g_cur[i] = run;
        run += v[j];
    }
}

// Scatter {src, raw weight}; no dinv dependency.
__global__ void __launch_bounds__(256) k_scatter(const void* __restrict__ ei,
                                                 const float* __restrict__ ew) {
    int is64 = g_is64;
    int e = blockIdx.x * blockDim.x + threadIdx.x;
    if (e >= NE) return;
    int r = idx_at(ei, e, is64);
    int c = idx_at(ei, (long long)NE + e, is64);
    int pos = atomicAdd(&g_cur[c], 1);
    g_csr[pos] = make_int2(r, __float_as_int(ew[e]));
}

// Coalesced segmented sum of weights -> deg -> dinv; premultiply x4 by dinv.
__global__ void __launch_bounds__(256) k_deg() {
    int wid = (blockIdx.x * blockDim.x + threadIdx.x) >> 5;
    int lane = threadIdx.x & 31;
    if (wid >= NN) return;
    int end = g_cur[wid];
    int n = g_cnt[wid];
    float s = 0.0f;
    for (int e = end - n + lane; e < end; e += 32)
        s += __int_as_float(g_csr[e].y);
#pragma unroll
    for (int off = 16; off; off >>= 1) s += __shfl_xor_sync(0xffffffffu, s, off);
    float di = rsqrtf(s + 1.0f);            // + self-loop weight
    if (lane == 0) {
        g_dinv[wid] = di;
        float4 v = g_x4[wid];
        v.x *= di; v.y *= di; v.z *= di;
        g_x4[wid] = v;                       // x4 is now dinv[i]*x[i]
    }
}

// Layer 1: s = sum(w * x4p[r]); agg = dinv[c]*(s + x4p[c]); h=relu(agg@W1+b1);
// store a1p = dinv[c]*h in fp16.
__global__ void __launch_bounds__(256) k_layer1(const float* __restrict__ W1,
                                                const float* __restrict__ b1) {
    int wid = (blockIdx.x * blockDim.x + threadIdx.x) >> 5;
    int lane = threadIdx.x & 31;
    if (wid >= NN) return;
    int end = g_cur[wid];
    int n = g_cnt[wid];
    float s0 = 0.f, s1 = 0.f, s2 = 0.f;
    for (int e = end - n + lane; e < end; e += 32) {
        int2 p = g_csr[e];
        float w = __int_as_float(p.y);
        float4 xr = g_x4[p.x];               // premultiplied; one LDG.128
        s0 += w * xr.x;
        s1 += w * xr.y;
        s2 += w * xr.z;
    }
#pragma unroll
    for (int off = 16; off; off >>= 1) {
        s0 += __shfl_xor_sync(0xffffffffu, s0, off);
        s1 += __shfl_xor_sync(0xffffffffu, s1, off);
        s2 += __shfl_xor_sync(0xffffffffu, s2, off);
    }
    float di = g_dinv[wid];
    float4 xs = g_x4[wid];                   // premultiplied self row
    s0 = di * (s0 + xs.x);
    s1 = di * (s1 + xs.y);
    s2 = di * (s2 + xs.z);
    if (lane < 16) {
        float o = b1[lane] + s0 * W1[lane] + s1 * W1[16 + lane] + s2 * W1[32 + lane];
        g_a1h[wid * 16 + lane] = __float2half(di * fmaxf(o, 0.0f));
    }
}

// Layer 2: 4 groups x 8 lanes, half2 per lane; agg = dinv[c]*(sum w*a1p[r] + a1p[c]);
// out = relu(agg@W2+b2); atomic pool.
__global__ void __launch_bounds__(256) k_layer2(const float* __restrict__ W2,
                                                const float* __restrict__ b2,
                                                const void* __restrict__ batch) {
    int is64 = g_is64;
    int wid = (blockIdx.x * blockDim.x + threadIdx.x) >> 5;
    int lane = threadIdx.x & 31;
    if (wid >= NN) return;
    const __half2* a1h2 = (const __half2*)g_a1h;
    int grp = lane >> 3;                     // 0..3
    int ff  = lane & 7;                      // feature pair index
    int end = g_cur[wid];
    int n = g_cnt[wid];
    float ax = 0.0f, ay = 0.0f;
    for (int e = end - n + grp; e < end; e += 4) {
        int2 p = g_csr[e];                   // broadcast within group
        float w = __int_as_float(p.y);
        float2 v = __half22float2(a1h2[p.x * 8 + ff]);
        ax += w * v.x;
        ay += w * v.y;
    }
#pragma unroll
    for (int off = 8; off <= 16; off <<= 1) {
        ax += __shfl_xor_sync(0xffffffffu, ax, off);
        ay += __shfl_xor_sync(0xffffffffu, ay, off);
    }
    float di = g_dinv[wid];
    float2 vs = __half22float2(a1h2[wid * 8 + ff]);  // premultiplied self
    ax = di * (ax + vs.x);
    ay = di * (ay + vs.y);
    int f = lane & 15;
    float o = b2[f];
#pragma unroll
    for (int k = 0; k < 16; k++) {
        float vk = __shfl_sync(0xffffffffu, (k & 1) ? ay : ax, k >> 1);
        o += vk * W2[k * 16 + f];
    }
    o = fmaxf(o, 0.0f);
    if (lane < 16) {
        int g = idx_at(batch, wid, is64);
        atomicAdd(&g_pool[g * 16 + f], o);
    }
}

__global__ void __launch_bounds__(256) k_final(const float* __restrict__ Wlin,
                                               const float* __restrict__ blin,
                                               float* __restrict__ out) {
    int t = blockIdx.x * blockDim.x + threadIdx.x;
    if (t >= NG * 7) return;
    int g = t / 7, j = t % 7;
    float o = blin[j];
#pragma unroll
    for (int k = 0; k < 16; k++) o += g_pool[g * 16 + k] * Wlin[k * 7 + j];
    out[t] = o;
}

// ---------------- launch ----------------

extern "C" void kernel_launch(void* const* d_in, const int* in_sizes, int n_in,
                              void* d_out, int out_size) {
    const float* x     = (const float*)d_in[0];
    const void*  ei    = d_in[1];
    const float* ew    = (const float*)d_in[2];
    const void*  batch = d_in[3];
    const float* W1    = (const float*)d_in[4];
    const float* b1    = (const float*)d_in[5];
    const float* W2    = (const float*)d_in[6];
    const float* b2    = (const float*)d_in[7];
    const float* Wlin  = (const float*)d_in[8];
    const float* blin  = (const float*)d_in[9];
    float* out = (float*)d_out;

    k_init    <<<(NN + 255) / 256, 256>>>(x);       // 0
    k_detect  <<<16, 256>>>((const int*)ei);        // 1
    k_pad     <<<1, 32>>>();                        // 2 (positions k_hist at profiled idx 3)
    k_hist    <<<(NE + 255) / 256, 256>>>(ei);      // 3
    k_scan1   <<<NSB, 256>>>();                     // 4
    k_scan2   <<<1, 128>>>();                       // 5
    k_scan3   <<<NSB, 256>>>();                     // 6
    k_scatter <<<(NE + 255) / 256, 256>>>(ei, ew);  // 7
    k_deg     <<<(NN * 32 + 255) / 256, 256>>>();   // 8
    k_layer1  <<<(NN * 32 + 255) / 256, 256>>>(W1, b1);        // 9
    k_layer2  <<<(NN * 32 + 255) / 256, 256>>>(W2, b2, batch); // 10
    k_final   <<<(NG * 7 + 255) / 256, 256>>>(Wlin, blin, out);// 11
}